// round 10
// baseline (speedup 1.0000x reference)
#include <cuda_runtime.h>
#include <math.h>

#define NG   512
#define IW   256
#define IH   256
#define HW   (IW*IH)
#define TW   32      // tile width
#define TH   16      // tile height
#define NPX  (TW*TH) // 512 pixels per tile
#define NTHR 1024    // 2 threads per pixel

// Dynamic shared memory layout (floats):
//   s_par : NG * 12   unordered hit records
//           [0]=mx [1]=my [2]=i00 [3]=i01 | [4]=i11 [5]=op [6]=dep [7]=idx |
//           [8]=xlo [9]=xhi [10]=ylo [11]=yhi
//   s_rgb : NG * 4    per-gaussian rgb (computed by warp-specialized half)
//   s_srt : NG * 16   depth-sorted records for compositing
//           [0]=mx [1]=my [2]=i00 [3]=i01 | [4]=i11 [5]=op [6]=r [7]=g |
//           [8]=b [9]=dep [10]=pad [11]=pad | [12..15]=bbox
//   s_part: 5 * NPX   back-half partial results (c0,c1,c2,dsum,T)
//   s_ord : NG ints
//   s_cnt : 1 int
#define SMEM_FLOATS (NG*12 + NG*4 + NG*16 + 5*NPX)
#define SMEM_BYTES  (SMEM_FLOATS*4 + NG*4 + 16)

__global__ void __launch_bounds__(NTHR, 1)
fused_render_kernel(const float* __restrict__ xyz,
                    const float* __restrict__ opa,
                    const float* __restrict__ feat,
                    const float* __restrict__ cov,
                    const float* __restrict__ Km,
                    const float* __restrict__ w2c,
                    const float* __restrict__ bg,
                    float* __restrict__ out)
{
    extern __shared__ float smem[];
    float (*s_par)[12] = (float(*)[12])smem;
    float (*s_rgb)[4]  = (float(*)[4]) (smem + NG*12);
    float (*s_srt)[16] = (float(*)[16])(smem + NG*16);
    float *s_part      = smem + NG*32;
    int   *s_ord       = (int*)(smem + NG*32 + 5*NPX);
    int   *s_cnt       = s_ord + NG;

    const int tid  = threadIdx.x;
    const int tx0  = blockIdx.x * TW;
    const int ty0  = blockIdx.y * TH;

    if (tid == 0) *s_cnt = 0;
    __syncthreads();

    if (tid < NG) {
        // ======== Geometry half: projection, covariance, bbox ========
        const int i = tid;

        float R[3][3], t[3], Kc[3][3];
        #pragma unroll
        for (int r = 0; r < 3; r++) {
            #pragma unroll
            for (int c = 0; c < 3; c++) {
                R[r][c]  = w2c[r*4 + c];
                Kc[r][c] = Km[r*3 + c];
            }
            t[r] = w2c[r*4 + 3];
        }
        const float fx = Kc[0][0], fy = Kc[1][1];

        const float px = xyz[i*3+0], py = xyz[i*3+1], pz = xyz[i*3+2];

        const float xc = R[0][0]*px + R[0][1]*py + R[0][2]*pz + t[0];
        const float yc = R[1][0]*px + R[1][1]*py + R[1][2]*pz + t[1];
        const float zc = R[2][0]*px + R[2][1]*py + R[2][2]*pz + t[2];
        const float depth = zc;

        const float hx = Kc[0][0]*xc + Kc[0][1]*yc + Kc[0][2]*zc;
        const float hy = Kc[1][0]*xc + Kc[1][1]*yc + Kc[1][2]*zc;
        const float hz = Kc[2][0]*xc + Kc[2][1]*yc + Kc[2][2]*zc;
        const float denom = fmaxf(hz, 1e-8f);
        const float mx = hx / denom;
        const float my = hy / denom;

        const float margin = 256.0f;
        const bool visible = (depth > 0.01f)
            && (mx > -margin) && (mx < (float)IW + margin)
            && (my > -margin) && (my < (float)IH + margin);

        const float tz = fmaxf(zc, 1e-8f);
        const float tz2 = tz*tz;
        const float J00 = fx/tz, J02 = -fx*xc/tz2;
        const float J11 = fy/tz, J12 = -fy*yc/tz2;

        float T0[3], T1[3];
        #pragma unroll
        for (int c = 0; c < 3; c++) {
            T0[c] = J00*R[0][c] + J02*R[2][c];
            T1[c] = J11*R[1][c] + J12*R[2][c];
        }
        float S[3][3];
        #pragma unroll
        for (int r = 0; r < 3; r++)
            #pragma unroll
            for (int c = 0; c < 3; c++)
                S[r][c] = cov[i*9 + r*3 + c];
        float v0[3], v1[3];
        #pragma unroll
        for (int r = 0; r < 3; r++) {
            v0[r] = S[r][0]*T0[0] + S[r][1]*T0[1] + S[r][2]*T0[2];
            v1[r] = S[r][0]*T1[0] + S[r][1]*T1[1] + S[r][2]*T1[2];
        }
        const float a = T0[0]*v0[0] + T0[1]*v0[1] + T0[2]*v0[2] + 0.3f;
        const float b = T1[0]*v0[0] + T1[1]*v0[1] + T1[2]*v0[2];
        const float d = T1[0]*v1[0] + T1[1]*v1[1] + T1[2]*v1[2] + 0.3f;

        const float det = a*d - b*b;
        const float tr  = a + d;
        const float lam = 0.5f * (tr + sqrtf(fmaxf(tr*tr - 4.0f*det, 0.0f)));
        const float radf = 3.0f * sqrtf(fmaxf(lam, 1e-8f));

        if (blockIdx.x == 0 && blockIdx.y == 0)
            out[5*HW + i] = visible ? radf : 0.0f;

        if (visible) {
            const float rad = fmaxf(radf, 1.0f);
            const float xlo = floorf(fminf(fmaxf(mx - rad,        0.0f), (float)IW));
            const float xhi = floorf(fminf(fmaxf(mx + rad + 1.0f, 0.0f), (float)IW));
            const float ylo = floorf(fminf(fmaxf(my - rad,        0.0f), (float)IH));
            const float yhi = floorf(fminf(fmaxf(my + rad + 1.0f, 0.0f), (float)IH));

            const float ftx0 = (float)tx0, ftx1 = (float)(tx0 + TW - 1);
            const float fty0 = (float)ty0, fty1 = (float)(ty0 + TH - 1);
            if (xhi > ftx0 && xlo <= ftx1 && yhi > fty0 && ylo <= fty1) {
                const float detc = fmaxf(det, 1e-10f);
                const int pos = atomicAdd(s_cnt, 1);
                float* dst = s_par[pos];
                dst[0]  = mx;        dst[1]  = my;
                dst[2]  =  d / detc; dst[3]  = -b / detc;
                dst[4]  =  a / detc; dst[5]  = opa[i];
                dst[6]  = depth;     dst[7]  = (float)i;
                dst[8]  = xlo;       dst[9]  = xhi;
                dst[10] = ylo;       dst[11] = yhi;
            }
        }
    } else {
        // ======== SH half: view direction + SH->RGB for all gaussians ========
        const int i = tid - NG;

        float R[3][3], t[3];
        #pragma unroll
        for (int r = 0; r < 3; r++) {
            #pragma unroll
            for (int c = 0; c < 3; c++)
                R[r][c] = w2c[r*4 + c];
            t[r] = w2c[r*4 + 3];
        }
        // cam_pos = -R^T t
        const float cpx = -(R[0][0]*t[0] + R[1][0]*t[1] + R[2][0]*t[2]);
        const float cpy = -(R[0][1]*t[0] + R[1][1]*t[1] + R[2][1]*t[2]);
        const float cpz = -(R[0][2]*t[0] + R[1][2]*t[1] + R[2][2]*t[2]);

        float vx = xyz[i*3+0] - cpx;
        float vy = xyz[i*3+1] - cpy;
        float vz = xyz[i*3+2] - cpz;
        const float inv_nrm = 1.0f / fmaxf(sqrtf(vx*vx + vy*vy + vz*vz), 1e-12f);
        vx *= inv_nrm; vy *= inv_nrm; vz *= inv_nrm;

        const float xx = vx*vx, yy = vy*vy, zz = vz*vz;
        const float xy_ = vx*vy, yz_ = vy*vz, xz_ = vx*vz;
        float B[16];
        B[0]  = 0.28209479177387814f;
        B[1]  = -0.4886025119029199f * vy;
        B[2]  =  0.4886025119029199f * vz;
        B[3]  = -0.4886025119029199f * vx;
        B[4]  =  1.0925484305920792f * xy_;
        B[5]  = -1.0925484305920792f * yz_;
        B[6]  =  0.31539156525252005f * (2.0f*zz - xx - yy);
        B[7]  = -1.0925484305920792f * xz_;
        B[8]  =  0.5462742152960396f * (xx - yy);
        B[9]  = -0.5900435899266435f * vy * (3.0f*xx - yy);
        B[10] =  2.890611442640554f  * xy_ * vz;
        B[11] = -0.4570457994644658f * vy * (4.0f*zz - xx - yy);
        B[12] =  0.3731763325901154f * vz * (2.0f*zz - 3.0f*xx - 3.0f*yy);
        B[13] = -0.4570457994644658f * vx * (4.0f*zz - xx - yy);
        B[14] =  1.445305721320277f  * vz * (xx - yy);
        B[15] = -0.5900435899266435f * vx * (xx - 3.0f*yy);

        // feat row: 48 consecutive floats, 16B-aligned (i*192 bytes)
        const float4* f4 = (const float4*)(feat + i*48);
        float fl[48];
        #pragma unroll
        for (int m = 0; m < 12; m++)
            *(float4*)&fl[m*4] = f4[m];

        #pragma unroll
        for (int c = 0; c < 3; c++) {
            float s = 0.0f;
            #pragma unroll
            for (int j = 0; j < 16; j++)
                s += B[j] * fl[j*3 + c];
            s_rgb[i][c] = fminf(fmaxf(s + 0.5f, 0.0f), 1.0f);
        }
    }
    __syncthreads();

    // ======== Stable rank sort by (depth, original index) ========
    const int n = *s_cnt;
    if (tid < n) {
        const float dep = s_par[tid][6];
        const float id  = s_par[tid][7];
        int rank = 0;
        for (int j = 0; j < n; j++) {
            const float dj = s_par[j][6];
            const float ij = s_par[j][7];
            rank += (dj < dep) || ((dj == dep) && (ij < id));
        }
        s_ord[rank] = tid;
    }
    __syncthreads();

    // ======== Permute into contiguous sorted buffer (+ inject rgb) ========
    for (int k = tid; k < n; k += NTHR) {
        const int src = s_ord[k];
        const float4 r0 = *(const float4*)&s_par[src][0]; // mx,my,i00,i01
        const float4 r1 = *(const float4*)&s_par[src][4]; // i11,op,dep,idx
        const float4 r2 = *(const float4*)&s_par[src][8]; // bbox
        const int orig = (int)r1.w;
        float* dst = s_srt[k];
        *(float4*)&dst[0]  = make_float4(r0.x, r0.y, r0.z, r0.w);
        *(float4*)&dst[4]  = make_float4(r1.x, r1.y, s_rgb[orig][0], s_rgb[orig][1]);
        *(float4*)&dst[8]  = make_float4(s_rgb[orig][2], r1.z, 0.0f, 0.0f);
        *(float4*)&dst[12] = r2;
    }
    __syncthreads();

    // ======== Split compositing: 2 threads per pixel ========
    const int px   = tid & (NPX - 1);
    const int half = tid >> 9;
    const float gx = (float)(tx0 + (px & (TW - 1)));
    const float gy = (float)(ty0 + (px >> 5));

    const int nA   = n >> 1;
    const int kbeg = half ? nA : 0;
    const int kend = half ? n  : nA;

    float T = 1.0f, c0 = 0.0f, c1 = 0.0f, c2 = 0.0f, dsum = 0.0f;

    for (int k = kbeg; k < kend; k++) {
        const float4 bb = *(const float4*)&s_srt[k][12];
        if (gx >= bb.x && gx < bb.y && gy >= bb.z && gy < bb.w) {
            const float4 a0 = *(const float4*)&s_srt[k][0]; // mx,my,i00,i01
            const float4 a1 = *(const float4*)&s_srt[k][4]; // i11,op,r,g
            const float4 a2 = *(const float4*)&s_srt[k][8]; // b,dep,-,-
            const float dx = gx - a0.x;
            const float dy = gy - a0.y;
            const float maha = a0.z*dx*dx + 2.0f*a0.w*dx*dy + a1.x*dy*dy;
            const float w = __expf(-0.5f * maha);
            const float alpha = fminf(a1.y * w, 0.99f);
            const float tc = T * alpha;
            c0   += tc * a1.z;
            c1   += tc * a1.w;
            c2   += tc * a2.x;
            dsum += tc * a2.y;
            T *= (1.0f - alpha);
            if (T < 1e-7f) break;
        }
    }

    if (half) {   // back half: publish partials
        s_part[0*NPX + px] = c0;
        s_part[1*NPX + px] = c1;
        s_part[2*NPX + px] = c2;
        s_part[3*NPX + px] = dsum;
        s_part[4*NPX + px] = T;
    }
    __syncthreads();

    if (!half) {  // front half: combine and store
        const float bc0 = s_part[0*NPX + px];
        const float bc1 = s_part[1*NPX + px];
        const float bc2 = s_part[2*NPX + px];
        const float bds = s_part[3*NPX + px];
        const float bT  = s_part[4*NPX + px];

        const float Tf = T * bT;
        const int idx = (ty0 + (px >> 5)) * IW + (tx0 + (px & (TW - 1)));
        out[0*HW + idx] = c0 + T*bc0 + bg[0] * Tf;
        out[1*HW + idx] = c1 + T*bc1 + bg[1] * Tf;
        out[2*HW + idx] = c2 + T*bc2 + bg[2] * Tf;
        out[3*HW + idx] = dsum + T*bds;
        out[4*HW + idx] = 1.0f - Tf;
    }
}

extern "C" void kernel_launch(void* const* d_in, const int* in_sizes, int n_in,
                              void* d_out, int out_size)
{
    const float* xyz  = (const float*)d_in[0];
    const float* opa  = (const float*)d_in[1];
    const float* feat = (const float*)d_in[2];
    const float* cov  = (const float*)d_in[3];
    const float* Km   = (const float*)d_in[4];
    const float* w2c  = (const float*)d_in[5];
    const float* bg   = (const float*)d_in[6];
    float* out = (float*)d_out;

    static bool attr_set = false;
    if (!attr_set) {
        cudaFuncSetAttribute(fused_render_kernel,
                             cudaFuncAttributeMaxDynamicSharedMemorySize,
                             SMEM_BYTES);
        attr_set = true;
    }

    dim3 grid(IW/TW, IH/TH);   // 8 x 16 = 128 blocks, one wave
    fused_render_kernel<<<grid, NTHR, SMEM_BYTES>>>(xyz, opa, feat, cov, Km,
                                                    w2c, bg, out);
}

// round 11
// speedup vs baseline: 1.2216x; 1.2216x over previous
#include <cuda_runtime.h>
#include <math.h>

#define NG   512
#define IW   256
#define IH   256
#define HW   (IW*IH)
#define TW   32      // tile width
#define TH   16      // tile height
#define NTHR 512

// Dynamic shared memory layout:
//   s_par : NG * 12 floats, unordered hit records
//           [0]=mx [1]=my [2]=i00 [3]=i01 | [4]=i11 [5]=op [6]=dep [7]=idx |
//           [8]=xlo [9]=xhi [10]=ylo [11]=yhi
//   s_srt : NG * 16 floats, depth-sorted records for compositing
//           [0]=mx [1]=my [2]=i00 [3]=i01 | [4]=i11 [5]=op [6]=r [7]=g |
//           [8]=b [9]=dep [10]=pad [11]=pad | [12..15]=bbox
//   s_cnt : 1 int
#define SMEM_BYTES ((NG*12 + NG*16)*4 + 16)

__global__ void __launch_bounds__(NTHR, 1)
fused_render_kernel(const float* __restrict__ xyz,
                    const float* __restrict__ opa,
                    const float* __restrict__ feat,
                    const float* __restrict__ cov,
                    const float* __restrict__ Km,
                    const float* __restrict__ w2c,
                    const float* __restrict__ bg,
                    float* __restrict__ out)
{
    extern __shared__ float smem[];
    float (*s_par)[12] = (float(*)[12])smem;
    float (*s_srt)[16] = (float(*)[16])(smem + NG*12);
    int   *s_cnt       = (int*)(smem + NG*12 + NG*16);

    const int tid  = threadIdx.x;
    const int lane = tid & 31;
    const int tx0  = blockIdx.x * TW;
    const int ty0  = blockIdx.y * TH;

    if (tid == 0) *s_cnt = 0;
    __syncthreads();

    // Camera matrices (broadcast loads)
    float R[3][3], t[3], Kc[3][3];
    #pragma unroll
    for (int r = 0; r < 3; r++) {
        #pragma unroll
        for (int c = 0; c < 3; c++) {
            R[r][c]  = w2c[r*4 + c];
            Kc[r][c] = Km[r*3 + c];
        }
        t[r] = w2c[r*4 + 3];
    }
    const float fx = Kc[0][0], fy = Kc[1][1];

    // ======== Phase A: geometry / conic / bbox, one gaussian per thread ====
    {
        const int i = tid;
        const float px = xyz[i*3+0], py = xyz[i*3+1], pz = xyz[i*3+2];

        const float xc = R[0][0]*px + R[0][1]*py + R[0][2]*pz + t[0];
        const float yc = R[1][0]*px + R[1][1]*py + R[1][2]*pz + t[1];
        const float zc = R[2][0]*px + R[2][1]*py + R[2][2]*pz + t[2];
        const float depth = zc;

        const float hx = Kc[0][0]*xc + Kc[0][1]*yc + Kc[0][2]*zc;
        const float hy = Kc[1][0]*xc + Kc[1][1]*yc + Kc[1][2]*zc;
        const float hz = Kc[2][0]*xc + Kc[2][1]*yc + Kc[2][2]*zc;
        const float inv_denom = __fdividef(1.0f, fmaxf(hz, 1e-8f));
        const float mx = hx * inv_denom;
        const float my = hy * inv_denom;

        const float margin = 256.0f;
        const bool visible = (depth > 0.01f)
            && (mx > -margin) && (mx < (float)IW + margin)
            && (my > -margin) && (my < (float)IH + margin);

        const float itz = __fdividef(1.0f, fmaxf(zc, 1e-8f));
        const float J00 = fx*itz,  J02 = -fx*xc*itz*itz;
        const float J11 = fy*itz,  J12 = -fy*yc*itz*itz;

        float T0[3], T1[3];
        #pragma unroll
        for (int c = 0; c < 3; c++) {
            T0[c] = J00*R[0][c] + J02*R[2][c];
            T1[c] = J11*R[1][c] + J12*R[2][c];
        }
        float S[3][3];
        #pragma unroll
        for (int r = 0; r < 3; r++)
            #pragma unroll
            for (int c = 0; c < 3; c++)
                S[r][c] = cov[i*9 + r*3 + c];
        float v0[3], v1[3];
        #pragma unroll
        for (int r = 0; r < 3; r++) {
            v0[r] = S[r][0]*T0[0] + S[r][1]*T0[1] + S[r][2]*T0[2];
            v1[r] = S[r][0]*T1[0] + S[r][1]*T1[1] + S[r][2]*T1[2];
        }
        const float a = T0[0]*v0[0] + T0[1]*v0[1] + T0[2]*v0[2] + 0.3f;
        const float b = T1[0]*v0[0] + T1[1]*v0[1] + T1[2]*v0[2];
        const float d = T1[0]*v1[0] + T1[1]*v1[1] + T1[2]*v1[2] + 0.3f;

        const float det = a*d - b*b;
        const float tr  = a + d;
        const float lam = 0.5f * (tr + sqrtf(fmaxf(tr*tr - 4.0f*det, 0.0f)));
        const float radf = 3.0f * sqrtf(fmaxf(lam, 1e-8f));

        if (blockIdx.x == 0 && blockIdx.y == 0)
            out[5*HW + i] = visible ? radf : 0.0f;

        // bbox (exact reference floor(clip()) semantics)
        const float rad = fmaxf(radf, 1.0f);
        const float xlo = floorf(fminf(fmaxf(mx - rad,        0.0f), (float)IW));
        const float xhi = floorf(fminf(fmaxf(mx + rad + 1.0f, 0.0f), (float)IW));
        const float ylo = floorf(fminf(fmaxf(my - rad,        0.0f), (float)IH));
        const float yhi = floorf(fminf(fmaxf(my + rad + 1.0f, 0.0f), (float)IH));

        const float ftx0 = (float)tx0, ftx1 = (float)(tx0 + TW - 1);
        const float fty0 = (float)ty0, fty1 = (float)(ty0 + TH - 1);
        const bool hit = visible
            && (xhi > ftx0) && (xlo <= ftx1) && (yhi > fty0) && (ylo <= fty1);

        // Warp-aggregated compaction: one atomic per warp
        const unsigned m = __ballot_sync(0xffffffffu, hit);
        if (m) {
            const int leader = __ffs(m) - 1;
            int base;
            if (lane == leader) base = atomicAdd(s_cnt, __popc(m));
            base = __shfl_sync(0xffffffffu, base, leader);
            if (hit) {
                const int pos = base + __popc(m & ((1u << lane) - 1u));
                const float rdet = __fdividef(1.0f, fmaxf(det, 1e-10f));
                float* dst = s_par[pos];
                *(float4*)&dst[0] = make_float4(mx, my, d*rdet, -b*rdet);
                *(float4*)&dst[4] = make_float4(a*rdet, opa[i], depth, (float)i);
                *(float4*)&dst[8] = make_float4(xlo, xhi, ylo, yhi);
            }
        }
    }
    __syncthreads();

    // ======== Phase B: rank + SH->RGB + scatter (hits only, dense) =========
    const int n  = *s_cnt;
    const int n4 = (n + 3) & ~3;

    if (tid < n) {
        const float4 r0 = *(const float4*)&s_par[tid][0];  // mx,my,i00,i01
        const float4 r1 = *(const float4*)&s_par[tid][4];  // i11,op,dep,idx
        const float4 r2 = *(const float4*)&s_par[tid][8];  // bbox
        const float dep = r1.z;
        const float id  = r1.w;

        // stable rank by (depth, original index)
        int rank = 0;
        for (int j = 0; j < n; j++) {
            const float2 kj = *(const float2*)&s_par[j][6];  // dep, idx
            rank += (kj.x < dep) || ((kj.x == dep) && (kj.y < id));
        }

        // SH -> RGB for this gaussian
        const int gi = (int)id;
        // cam_pos = -R^T t
        const float cpx = -(R[0][0]*t[0] + R[1][0]*t[1] + R[2][0]*t[2]);
        const float cpy = -(R[0][1]*t[0] + R[1][1]*t[1] + R[2][1]*t[2]);
        const float cpz = -(R[0][2]*t[0] + R[1][2]*t[1] + R[2][2]*t[2]);

        float vx = xyz[gi*3+0] - cpx;
        float vy = xyz[gi*3+1] - cpy;
        float vz = xyz[gi*3+2] - cpz;
        const float inv_nrm = rsqrtf(fmaxf(vx*vx + vy*vy + vz*vz, 1e-24f));
        vx *= inv_nrm; vy *= inv_nrm; vz *= inv_nrm;

        const float xx = vx*vx, yy = vy*vy, zz = vz*vz;
        const float xy_ = vx*vy, yz_ = vy*vz, xz_ = vx*vz;
        float B[16];
        B[0]  = 0.28209479177387814f;
        B[1]  = -0.4886025119029199f * vy;
        B[2]  =  0.4886025119029199f * vz;
        B[3]  = -0.4886025119029199f * vx;
        B[4]  =  1.0925484305920792f * xy_;
        B[5]  = -1.0925484305920792f * yz_;
        B[6]  =  0.31539156525252005f * (2.0f*zz - xx - yy);
        B[7]  = -1.0925484305920792f * xz_;
        B[8]  =  0.5462742152960396f * (xx - yy);
        B[9]  = -0.5900435899266435f * vy * (3.0f*xx - yy);
        B[10] =  2.890611442640554f  * xy_ * vz;
        B[11] = -0.4570457994644658f * vy * (4.0f*zz - xx - yy);
        B[12] =  0.3731763325901154f * vz * (2.0f*zz - 3.0f*xx - 3.0f*yy);
        B[13] = -0.4570457994644658f * vx * (4.0f*zz - xx - yy);
        B[14] =  1.445305721320277f  * vz * (xx - yy);
        B[15] = -0.5900435899266435f * vx * (xx - 3.0f*yy);

        const float4* f4 = (const float4*)(feat + gi*48);
        float fl[48];
        #pragma unroll
        for (int q = 0; q < 12; q++)
            *(float4*)&fl[q*4] = f4[q];

        float rgb[3];
        #pragma unroll
        for (int c = 0; c < 3; c++) {
            float s = 0.0f;
            #pragma unroll
            for (int j = 0; j < 16; j++)
                s += B[j] * fl[j*3 + c];
            rgb[c] = fminf(fmaxf(s + 0.5f, 0.0f), 1.0f);
        }

        float* dst = s_srt[rank];
        *(float4*)&dst[0]  = make_float4(r0.x, r0.y, r0.z, r0.w);
        *(float4*)&dst[4]  = make_float4(r1.x, r1.y, rgb[0], rgb[1]);
        *(float4*)&dst[8]  = make_float4(rgb[2], dep, 0.0f, 0.0f);
        *(float4*)&dst[12] = r2;
    } else if (tid < n4) {
        // pad with never-hit bboxes so the composite loop can run in 4s
        *(float4*)&s_srt[tid][12] = make_float4(1e9f, -1e9f, 1e9f, -1e9f);
    }
    __syncthreads();

    // ======== Phase C: per-pixel front-to-back compositing =================
    const float gx = (float)(tx0 + (tid & (TW - 1)));
    const float gy = (float)(ty0 + (tid >> 5));
    const float bg0 = bg[0], bg1 = bg[1], bg2 = bg[2];

    float T = 1.0f, c0 = 0.0f, c1 = 0.0f, c2 = 0.0f, dsum = 0.0f;

    for (int k0 = 0; k0 < n4; k0 += 4) {
        #pragma unroll
        for (int u = 0; u < 4; u++) {
            const int k = k0 + u;
            const float4 bb = *(const float4*)&s_srt[k][12];
            if (gx >= bb.x && gx < bb.y && gy >= bb.z && gy < bb.w) {
                const float4 a0 = *(const float4*)&s_srt[k][0]; // mx,my,i00,i01
                const float4 a1 = *(const float4*)&s_srt[k][4]; // i11,op,r,g
                const float4 a2 = *(const float4*)&s_srt[k][8]; // b,dep,-,-
                const float dx = gx - a0.x;
                const float dy = gy - a0.y;
                const float maha = a0.z*dx*dx + 2.0f*a0.w*dx*dy + a1.x*dy*dy;
                const float w = __expf(-0.5f * maha);
                const float alpha = fminf(a1.y * w, 0.99f);
                const float tc = T * alpha;
                c0   += tc * a1.z;
                c1   += tc * a1.w;
                c2   += tc * a2.x;
                dsum += tc * a2.y;
                T *= (1.0f - alpha);
            }
        }
        if (T < 1e-7f) break;   // break check amortized over 4 iterations
    }

    const int idx = (ty0 + (tid >> 5)) * IW + (tx0 + (tid & (TW - 1)));
    out[0*HW + idx] = c0 + bg0 * T;
    out[1*HW + idx] = c1 + bg1 * T;
    out[2*HW + idx] = c2 + bg2 * T;
    out[3*HW + idx] = dsum;
    out[4*HW + idx] = 1.0f - T;
}

extern "C" void kernel_launch(void* const* d_in, const int* in_sizes, int n_in,
                              void* d_out, int out_size)
{
    const float* xyz  = (const float*)d_in[0];
    const float* opa  = (const float*)d_in[1];
    const float* feat = (const float*)d_in[2];
    const float* cov  = (const float*)d_in[3];
    const float* Km   = (const float*)d_in[4];
    const float* w2c  = (const float*)d_in[5];
    const float* bg   = (const float*)d_in[6];
    float* out = (float*)d_out;

    static bool attr_set = false;
    if (!attr_set) {
        cudaFuncSetAttribute(fused_render_kernel,
                             cudaFuncAttributeMaxDynamicSharedMemorySize,
                             SMEM_BYTES);
        attr_set = true;
    }

    dim3 grid(IW/TW, IH/TH);   // 8 x 16 = 128 blocks, one wave
    fused_render_kernel<<<grid, NTHR, SMEM_BYTES>>>(xyz, opa, feat, cov, Km,
                                                    w2c, bg, out);
}

// round 12
// speedup vs baseline: 1.5055x; 1.2325x over previous
#include <cuda_runtime.h>
#include <math.h>

#define NG   512
#define IW   256
#define IH   256
#define HW   (IW*IH)
#define TW   32      // tile width
#define TH   16      // tile height
#define NTHR 512

// Dynamic shared memory layout:
//   s_par : NG * 12 floats, unordered hit records
//           [0]=mx [1]=my [2]=i00 [3]=i01 | [4]=i11 [5]=op [6]=dep [7]=idx |
//           [8]=xlo [9]=xhi [10]=ylo [11]=yhi
//   s_srt : NG * 16 floats, depth-sorted records for compositing
//           [0]=mx [1]=my [2]=i00 [3]=2*i01 | [4]=i11 [5]=op [6]=r [7]=g |
//           [8]=b [9]=dep [10]=pad [11]=pad | [12..15]=bbox
//   s_cnt : 1 int
#define SMEM_BYTES ((NG*12 + NG*16)*4 + 16)

__global__ void __launch_bounds__(NTHR, 1)
fused_render_kernel(const float* __restrict__ xyz,
                    const float* __restrict__ opa,
                    const float* __restrict__ feat,
                    const float* __restrict__ cov,
                    const float* __restrict__ Km,
                    const float* __restrict__ w2c,
                    const float* __restrict__ bg,
                    float* __restrict__ out)
{
    extern __shared__ float smem[];
    float (*s_par)[12] = (float(*)[12])smem;
    float (*s_srt)[16] = (float(*)[16])(smem + NG*12);
    int   *s_cnt       = (int*)(smem + NG*12 + NG*16);

    const int tid  = threadIdx.x;
    const int lane = tid & 31;
    const int tx0  = blockIdx.x * TW;
    const int ty0  = blockIdx.y * TH;

    if (tid == 0) *s_cnt = 0;
    __syncthreads();

    // Camera matrices (broadcast loads)
    float R[3][3], t[3], Kc[3][3];
    #pragma unroll
    for (int r = 0; r < 3; r++) {
        #pragma unroll
        for (int c = 0; c < 3; c++) {
            R[r][c]  = w2c[r*4 + c];
            Kc[r][c] = Km[r*3 + c];
        }
        t[r] = w2c[r*4 + 3];
    }
    const float fx = Kc[0][0], fy = Kc[1][1];

    // ======== Phase A: geometry / conic / bbox, one gaussian per thread ====
    {
        const int i = tid;
        const float px = xyz[i*3+0], py = xyz[i*3+1], pz = xyz[i*3+2];

        const float xc = R[0][0]*px + R[0][1]*py + R[0][2]*pz + t[0];
        const float yc = R[1][0]*px + R[1][1]*py + R[1][2]*pz + t[1];
        const float zc = R[2][0]*px + R[2][1]*py + R[2][2]*pz + t[2];
        const float depth = zc;

        const float hx = Kc[0][0]*xc + Kc[0][1]*yc + Kc[0][2]*zc;
        const float hy = Kc[1][0]*xc + Kc[1][1]*yc + Kc[1][2]*zc;
        const float hz = Kc[2][0]*xc + Kc[2][1]*yc + Kc[2][2]*zc;
        const float inv_denom = __fdividef(1.0f, fmaxf(hz, 1e-8f));
        const float mx = hx * inv_denom;
        const float my = hy * inv_denom;

        const float margin = 256.0f;
        const bool visible = (depth > 0.01f)
            && (mx > -margin) && (mx < (float)IW + margin)
            && (my > -margin) && (my < (float)IH + margin);

        const float itz = __fdividef(1.0f, fmaxf(zc, 1e-8f));
        const float J00 = fx*itz,  J02 = -fx*xc*itz*itz;
        const float J11 = fy*itz,  J12 = -fy*yc*itz*itz;

        float T0[3], T1[3];
        #pragma unroll
        for (int c = 0; c < 3; c++) {
            T0[c] = J00*R[0][c] + J02*R[2][c];
            T1[c] = J11*R[1][c] + J12*R[2][c];
        }
        float S[3][3];
        #pragma unroll
        for (int r = 0; r < 3; r++)
            #pragma unroll
            for (int c = 0; c < 3; c++)
                S[r][c] = cov[i*9 + r*3 + c];
        float v0[3], v1[3];
        #pragma unroll
        for (int r = 0; r < 3; r++) {
            v0[r] = S[r][0]*T0[0] + S[r][1]*T0[1] + S[r][2]*T0[2];
            v1[r] = S[r][0]*T1[0] + S[r][1]*T1[1] + S[r][2]*T1[2];
        }
        const float a = T0[0]*v0[0] + T0[1]*v0[1] + T0[2]*v0[2] + 0.3f;
        const float b = T1[0]*v0[0] + T1[1]*v0[1] + T1[2]*v0[2];
        const float d = T1[0]*v1[0] + T1[1]*v1[1] + T1[2]*v1[2] + 0.3f;

        const float det = a*d - b*b;
        const float tr  = a + d;
        const float lam = 0.5f * (tr + sqrtf(fmaxf(tr*tr - 4.0f*det, 0.0f)));
        const float radf = 3.0f * sqrtf(fmaxf(lam, 1e-8f));

        if (blockIdx.x == 0 && blockIdx.y == 0)
            out[5*HW + i] = visible ? radf : 0.0f;

        // bbox (exact reference floor(clip()) semantics)
        const float rad = fmaxf(radf, 1.0f);
        const float xlo = floorf(fminf(fmaxf(mx - rad,        0.0f), (float)IW));
        const float xhi = floorf(fminf(fmaxf(mx + rad + 1.0f, 0.0f), (float)IW));
        const float ylo = floorf(fminf(fmaxf(my - rad,        0.0f), (float)IH));
        const float yhi = floorf(fminf(fmaxf(my + rad + 1.0f, 0.0f), (float)IH));

        const float ftx0 = (float)tx0, ftx1 = (float)(tx0 + TW - 1);
        const float fty0 = (float)ty0, fty1 = (float)(ty0 + TH - 1);
        const bool hit = visible
            && (xhi > ftx0) && (xlo <= ftx1) && (yhi > fty0) && (ylo <= fty1);

        // Warp-aggregated compaction: one atomic per warp
        const unsigned m = __ballot_sync(0xffffffffu, hit);
        if (m) {
            const int leader = __ffs(m) - 1;
            int base;
            if (lane == leader) base = atomicAdd(s_cnt, __popc(m));
            base = __shfl_sync(0xffffffffu, base, leader);
            if (hit) {
                const int pos = base + __popc(m & ((1u << lane) - 1u));
                const float rdet = __fdividef(1.0f, fmaxf(det, 1e-10f));
                float* dst = s_par[pos];
                *(float4*)&dst[0] = make_float4(mx, my, d*rdet, -b*rdet);
                *(float4*)&dst[4] = make_float4(a*rdet, opa[i], depth, (float)i);
                *(float4*)&dst[8] = make_float4(xlo, xhi, ylo, yhi);
            }
        }
    }
    __syncthreads();

    // ======== Phase B: rank + SH->RGB + scatter (hits only, dense) =========
    const int n  = *s_cnt;
    const int n4 = (n + 3) & ~3;

    if (tid < n) {
        const float4 r0 = *(const float4*)&s_par[tid][0];  // mx,my,i00,i01
        const float4 r1 = *(const float4*)&s_par[tid][4];  // i11,op,dep,idx
        const float4 r2 = *(const float4*)&s_par[tid][8];  // bbox
        const float dep = r1.z;
        const float id  = r1.w;

        // stable rank by (depth, original index)
        int rank = 0;
        for (int j = 0; j < n; j++) {
            const float2 kj = *(const float2*)&s_par[j][6];  // dep, idx
            rank += (kj.x < dep) || ((kj.x == dep) && (kj.y < id));
        }

        // SH -> RGB for this gaussian
        const int gi = (int)id;
        // cam_pos = -R^T t
        const float cpx = -(R[0][0]*t[0] + R[1][0]*t[1] + R[2][0]*t[2]);
        const float cpy = -(R[0][1]*t[0] + R[1][1]*t[1] + R[2][1]*t[2]);
        const float cpz = -(R[0][2]*t[0] + R[1][2]*t[1] + R[2][2]*t[2]);

        float vx = xyz[gi*3+0] - cpx;
        float vy = xyz[gi*3+1] - cpy;
        float vz = xyz[gi*3+2] - cpz;
        const float inv_nrm = rsqrtf(fmaxf(vx*vx + vy*vy + vz*vz, 1e-24f));
        vx *= inv_nrm; vy *= inv_nrm; vz *= inv_nrm;

        const float xx = vx*vx, yy = vy*vy, zz = vz*vz;
        const float xy_ = vx*vy, yz_ = vy*vz, xz_ = vx*vz;
        float B[16];
        B[0]  = 0.28209479177387814f;
        B[1]  = -0.4886025119029199f * vy;
        B[2]  =  0.4886025119029199f * vz;
        B[3]  = -0.4886025119029199f * vx;
        B[4]  =  1.0925484305920792f * xy_;
        B[5]  = -1.0925484305920792f * yz_;
        B[6]  =  0.31539156525252005f * (2.0f*zz - xx - yy);
        B[7]  = -1.0925484305920792f * xz_;
        B[8]  =  0.5462742152960396f * (xx - yy);
        B[9]  = -0.5900435899266435f * vy * (3.0f*xx - yy);
        B[10] =  2.890611442640554f  * xy_ * vz;
        B[11] = -0.4570457994644658f * vy * (4.0f*zz - xx - yy);
        B[12] =  0.3731763325901154f * vz * (2.0f*zz - 3.0f*xx - 3.0f*yy);
        B[13] = -0.4570457994644658f * vx * (4.0f*zz - xx - yy);
        B[14] =  1.445305721320277f  * vz * (xx - yy);
        B[15] = -0.5900435899266435f * vx * (xx - 3.0f*yy);

        const float4* f4 = (const float4*)(feat + gi*48);
        float fl[48];
        #pragma unroll
        for (int q = 0; q < 12; q++)
            *(float4*)&fl[q*4] = f4[q];

        float rgb[3];
        #pragma unroll
        for (int c = 0; c < 3; c++) {
            float s = 0.0f;
            #pragma unroll
            for (int j = 0; j < 16; j++)
                s += B[j] * fl[j*3 + c];
            rgb[c] = fminf(fmaxf(s + 0.5f, 0.0f), 1.0f);
        }

        float* dst = s_srt[rank];
        *(float4*)&dst[0]  = make_float4(r0.x, r0.y, r0.z, 2.0f * r0.w);
        *(float4*)&dst[4]  = make_float4(r1.x, r1.y, rgb[0], rgb[1]);
        *(float4*)&dst[8]  = make_float4(rgb[2], dep, 0.0f, 0.0f);
        *(float4*)&dst[12] = r2;
    } else if (tid < n4) {
        // fully-zeroed padding record: op=0 -> alpha=0, bbox empty, maha=0
        float* dst = s_srt[tid];
        const float4 z = make_float4(0.0f, 0.0f, 0.0f, 0.0f);
        *(float4*)&dst[0]  = z;
        *(float4*)&dst[4]  = z;
        *(float4*)&dst[8]  = z;
        *(float4*)&dst[12] = make_float4(1e9f, -1e9f, 1e9f, -1e9f);
    }
    __syncthreads();

    // ======== Phase C: branchless per-pixel front-to-back compositing ======
    const float gx = (float)(tx0 + (tid & (TW - 1)));
    const float gy = (float)(ty0 + (tid >> 5));
    const float bg0 = bg[0], bg1 = bg[1], bg2 = bg[2];

    float T = 1.0f, c0 = 0.0f, c1 = 0.0f, c2 = 0.0f, dsum = 0.0f;

    for (int k0 = 0; k0 < n4; k0 += 4) {
        #pragma unroll
        for (int u = 0; u < 4; u++) {
            const int k = k0 + u;
            // Unconditional broadcast loads -> full pipelining, no divergence
            const float4 a0 = *(const float4*)&s_srt[k][0];  // mx,my,i00,2*i01
            const float4 a1 = *(const float4*)&s_srt[k][4];  // i11,op,r,g
            const float4 a2 = *(const float4*)&s_srt[k][8];  // b,dep,-,-
            const float4 bb = *(const float4*)&s_srt[k][12]; // bbox

            const bool covering = (gx >= bb.x) && (gx < bb.y) &&
                                  (gy >= bb.z) && (gy < bb.w);
            const float dx = gx - a0.x;
            const float dy = gy - a0.y;
            const float maha = a0.z*dx*dx + a0.w*dx*dy + a1.x*dy*dy;
            float alpha = fminf(a1.y * __expf(-0.5f * maha), 0.99f);
            alpha = covering ? alpha : 0.0f;      // select, not branch
            const float tc = T * alpha;
            c0   += tc * a1.z;
            c1   += tc * a1.w;
            c2   += tc * a2.x;
            dsum += tc * a2.y;
            T    -= tc;                            // = T * (1 - alpha)
        }
        // warp-uniform early exit, amortized over 4 iterations
        if (__all_sync(0xffffffffu, T < 1e-7f)) break;
    }

    const int idx = (ty0 + (tid >> 5)) * IW + (tx0 + (tid & (TW - 1)));
    out[0*HW + idx] = c0 + bg0 * T;
    out[1*HW + idx] = c1 + bg1 * T;
    out[2*HW + idx] = c2 + bg2 * T;
    out[3*HW + idx] = dsum;
    out[4*HW + idx] = 1.0f - T;
}

extern "C" void kernel_launch(void* const* d_in, const int* in_sizes, int n_in,
                              void* d_out, int out_size)
{
    const float* xyz  = (const float*)d_in[0];
    const float* opa  = (const float*)d_in[1];
    const float* feat = (const float*)d_in[2];
    const float* cov  = (const float*)d_in[3];
    const float* Km   = (const float*)d_in[4];
    const float* w2c  = (const float*)d_in[5];
    const float* bg   = (const float*)d_in[6];
    float* out = (float*)d_out;

    static bool attr_set = false;
    if (!attr_set) {
        cudaFuncSetAttribute(fused_render_kernel,
                             cudaFuncAttributeMaxDynamicSharedMemorySize,
                             SMEM_BYTES);
        attr_set = true;
    }

    dim3 grid(IW/TW, IH/TH);   // 8 x 16 = 128 blocks, one wave
    fused_render_kernel<<<grid, NTHR, SMEM_BYTES>>>(xyz, opa, feat, cov, Km,
                                                    w2c, bg, out);
}